// round 9
// baseline (speedup 1.0000x reference)
#include <cuda_runtime.h>
#include <cstdint>

// Patcher: x (8,3,1024,1024) fp32, patch=24, stride=16, reflect pad m=4.
// out[((b*64+ph)*64+pw)*1728 + (i*24+j)*3 + c] = x[b,c,ry,rx]
//   ry=reflect(ph*16+i-4), rx=reflect(pw*16+j-4); reflect: q<0->-q, q>1023->2046-q.
//
// Block (512 thr) = (b, ph, pg): 4 consecutive patches (pw = 4*pg..4*pg+3).
//  Phase 1  : coalesced LDG.128 x3 (channel planes) -> transpose -> STS.128 x3
//             into tile smem [r][x][c] (c-fastest), 72 cols.
//  Phase 1.5: LDS.128 tile -> STS.128 into o_stage (exact output layout).
//  Phase 2  : ONE cp.async.bulk (TMA) 27648 B smem -> contiguous gmem region.
// smem 47.25 KB static; 4 CTAs/SM x 16 warps = 64 warps = full occupancy.

static constexpr unsigned HWu = 1024u * 1024u;
static constexpr long long TOTAL_ELEMS = 56623104LL;
static constexpr unsigned ROW_F4 = 54u;               // 72*3/4 float4 per tile row
static constexpr unsigned TILE_F4 = 24u * ROW_F4;     // 1296 f4 = 20736 B
static constexpr unsigned N_GROUPS = 24u * 18u;       // (r, xg) = 432
static constexpr unsigned OUT_F4 = 4u * 432u;         // 1728 f4 = 27648 B
static constexpr unsigned OUT_BYTES = OUT_F4 * 16u;   // 27648

__device__ __forceinline__ int reflect_idx(int q) {
    q = (q < 0) ? -q : q;
    q = (q > 1023) ? (2046 - q) : q;
    return q;
}

__global__ void __launch_bounds__(512, 4)
patcher_kernel(const float* __restrict__ x, float* __restrict__ out,
               unsigned out_size) {
    __shared__ float4 s4[TILE_F4];        // staged tile, c-fastest
    __shared__ float4 o_stage[OUT_F4];    // exact output layout

    unsigned bid = blockIdx.x;
    unsigned tid = threadIdx.x;
    unsigned pg = bid & 15u;         // 16 groups of 4 patches
    unsigned ph = (bid >> 4) & 63u;
    unsigned b  = bid >> 10;

    if (bid == 0 && tid < 32u) {     // tail fill: flattened (nH,nW)=(64,64)
        unsigned idx = (unsigned)TOTAL_ELEMS + tid;
        if (idx < out_size) out[idx] = 64.0f;
    }

    // ---- Phase 1: stage + in-lane transpose (coalesced reads) ----
    const float* xb = x + (size_t)b * (3u * HWu);
    int ybase = (int)(ph << 4) - 4;
    int gx0   = (int)(pg << 6) - 4;   // tile x origin (pg*64 - 4)

    if (tid < N_GROUPS) {
        unsigned r  = tid / 18u;
        unsigned xg = tid - r * 18u;
        int y  = reflect_idx(ybase + (int)r);
        int gx = gx0 + (int)(xg << 2);

        const float* p = xb + (unsigned)y * 1024u;
        float4 a0, a1, a2;
        if (gx >= 0 && gx <= 1020) {
            a0 = *reinterpret_cast<const float4*>(p + gx);
            a1 = *reinterpret_cast<const float4*>(p + HWu + gx);
            a2 = *reinterpret_cast<const float4*>(p + 2u * HWu + gx);
        } else {
            int x0 = reflect_idx(gx), x1 = reflect_idx(gx + 1);
            int x2 = reflect_idx(gx + 2), x3 = reflect_idx(gx + 3);
            a0.x = p[x0]; a0.y = p[x1]; a0.z = p[x2]; a0.w = p[x3];
            const float* q1 = p + HWu;
            a1.x = q1[x0]; a1.y = q1[x1]; a1.z = q1[x2]; a1.w = q1[x3];
            const float* q2 = p + 2u * HWu;
            a2.x = q2[x0]; a2.y = q2[x1]; a2.z = q2[x2]; a2.w = q2[x3];
        }
        unsigned sbase = r * ROW_F4 + xg * 3u;
        float4 t0, t1, t2;
        t0.x = a0.x; t0.y = a1.x; t0.z = a2.x; t0.w = a0.y;
        t1.x = a1.y; t1.y = a2.y; t1.z = a0.z; t1.w = a1.z;
        t2.x = a2.z; t2.y = a0.w; t2.z = a1.w; t2.w = a2.w;
        s4[sbase + 0] = t0;
        s4[sbase + 1] = t1;
        s4[sbase + 2] = t2;
    }
    __syncthreads();

    // ---- Phase 1.5: rearrange tile -> output layout (smem to smem) ----
    #pragma unroll
    for (unsigned it = 0; it < 4; ++it) {
        unsigned idx = tid + it * 512u;
        if (idx < OUT_F4) {
            unsigned pl  = idx / 432u;          // local patch 0..3
            unsigned rem = idx - pl * 432u;
            unsigned i   = rem / 18u;           // patch row
            unsigned off = rem - i * 18u;       // float4 in row
            o_stage[idx] = s4[i * ROW_F4 + pl * 12u + off];
        }
    }
    __syncthreads();

    // ---- Phase 2: single TMA bulk store of the contiguous region ----
    if (tid == 0) {
        unsigned patch0 = (b << 12) + (ph << 6) + (pg << 2);
        float4* gdst = reinterpret_cast<float4*>(out) + (size_t)patch0 * 432u;

        uint32_t saddr;
        asm("{ .reg .u64 t; cvta.to.shared.u64 t, %1; cvt.u32.u64 %0, t; }"
            : "=r"(saddr) : "l"(o_stage));
        asm volatile("fence.proxy.async.shared::cta;" ::: "memory");
        asm volatile(
            "cp.async.bulk.global.shared::cta.bulk_group [%0], [%1], %2;"
            :: "l"(gdst), "r"(saddr), "r"(OUT_BYTES) : "memory");
        asm volatile("cp.async.bulk.commit_group;" ::: "memory");
        asm volatile("cp.async.bulk.wait_group.read 0;" ::: "memory");
    }
}

extern "C" void kernel_launch(void* const* d_in, const int* in_sizes, int n_in,
                              void* d_out, int out_size) {
    const float* x = (const float*)d_in[0];
    float* out = (float*)d_out;
    patcher_kernel<<<8192, 512>>>(x, out, (unsigned)out_size);
}